// round 2
// baseline (speedup 1.0000x reference)
#include <cuda_runtime.h>
#include <cstdint>

#define PP 32      // num networks
#define HH 128     // hidden
#define BB 32      // batch
#define TT 256     // seq len
#define CHUNK 4    // CTAs per network (cluster size)
#define JJ 32      // h outputs per CTA
#define NTHREADS 256
#define BT 4       // batches per thread

// ---- shared memory layout (float offsets) ----
#define OFF_WHH   0                       // [4][32 kc][32 j][4 ki]  = 16384
#define SZ_WHH    (4*32*32*4)
#define OFF_WIH   (OFF_WHH + SZ_WHH)      // [4][8 dc][32 j][4 di]   = 4096
#define SZ_WIH    (4*8*32*4)
#define OFF_H0    (OFF_WIH + SZ_WIH)      // [32 b][128 k]           = 4096
#define OFF_H1    (OFF_H0 + BB*HH)        //                         = 4096
#define OFF_X     (OFF_H1 + BB*HH)        // [32 b][32 d]            = 1024
#define OFF_BIAS  (OFF_X + BB*PP)         // [4][32]                 = 128
#define OFF_WOUT  (OFF_BIAS + 4*JJ)       // [32]                    = 32
#define SMEM_FLOATS (OFF_WOUT + JJ)       // 29856 floats
#define SMEM_BYTES (SMEM_FLOATS * 4)      // 119424 bytes

__device__ __forceinline__ float sigf(float x) {
    return 1.0f / (1.0f + __expf(-x));
}
__device__ __forceinline__ float tanhfast(float x) {
    return 2.0f / (1.0f + __expf(-2.0f * x)) - 1.0f;
}

__global__ void init_out_kernel(float* __restrict__ out, const float* __restrict__ b_out) {
    int i = blockIdx.x * blockDim.x + threadIdx.x;
    if (i < BB * TT * PP) out[i] = b_out[i & (PP - 1)];
}

extern __shared__ float smem[];

__global__ void __cluster_dims__(CHUNK, 1, 1) __launch_bounds__(NTHREADS, 1)
clstm_kernel(const float* __restrict__ Xg,
             const float* __restrict__ Wih,
             const float* __restrict__ Whh,
             const float* __restrict__ bih,
             const float* __restrict__ bhh,
             const float* __restrict__ Wout,
             float* __restrict__ out)
{
    const int tid  = threadIdx.x;
    const int lane = tid & 31;           // j within this CTA's slice
    const int warp = tid >> 5;           // 8 warps
    const int b0   = warp * BT;          // batches [b0, b0+4)

    uint32_t rank;
    asm("mov.u32 %0, %%cluster_ctarank;" : "=r"(rank));
    const int n  = blockIdx.x >> 2;      // network id
    const int j0 = (int)rank * JJ;       // global j offset of this CTA's slice

    float* Whh_s  = smem + OFF_WHH;
    float* Wih_s  = smem + OFF_WIH;
    float* X_s    = smem + OFF_X;
    float* bias_s = smem + OFF_BIAS;
    float* Wout_s = smem + OFF_WOUT;

    // ---- stage weights (transposed for conflict-free lane loads) ----
    // W_hh rows {g*H + j0 + j}, k in [0,128) -> Whh_s[((g*32+kc)*32 + j)*4 + ki]
    for (int idx = tid; idx < 4 * HH * JJ; idx += NTHREADS) {
        int g   = idx / (HH * JJ);
        int rem = idx - g * (HH * JJ);
        int k   = rem / JJ;
        int j   = rem - k * JJ;
        float v = Whh[((size_t)n * 4 * HH + g * HH + j0 + j) * HH + k];
        Whh_s[((g * 32 + (k >> 2)) * JJ + j) * 4 + (k & 3)] = v;
    }
    // W_ih rows {g*H + j0 + j}, d in [0,32) -> Wih_s[((g*8+dc)*32 + j)*4 + di]
    for (int idx = tid; idx < 4 * PP * JJ; idx += NTHREADS) {
        int g   = idx / (PP * JJ);
        int rem = idx - g * (PP * JJ);
        int j   = rem / PP;
        int d   = rem - j * PP;
        float v = Wih[((size_t)n * 4 * HH + g * HH + j0 + j) * PP + d];
        Wih_s[((g * 8 + (d >> 2)) * JJ + j) * 4 + (d & 3)] = v;
    }
    for (int idx = tid; idx < 4 * JJ; idx += NTHREADS) {
        int g = idx / JJ, j = idx - g * JJ;
        int row = n * 4 * HH + g * HH + j0 + j;
        bias_s[g * JJ + j] = bih[row] + bhh[row];
    }
    if (tid < JJ) Wout_s[tid] = Wout[n * HH + j0 + tid];
    // zero both h double-buffers
    for (int idx = tid; idx < 2 * BB * HH; idx += NTHREADS) smem[OFF_H0 + idx] = 0.0f;

    // smem base as u32 + peer base addresses (mapa is offset-linear)
    uint32_t sbase;
    asm("{ .reg .u64 t0; cvta.to.shared.u64 t0, %1; cvt.u32.u64 %0, t0; }"
        : "=r"(sbase) : "l"(smem));
    uint32_t peer_base[CHUNK];
#pragma unroll
    for (int r = 0; r < CHUNK; ++r) {
        asm("mapa.shared::cluster.u32 %0, %1, %2;" : "=r"(peer_base[r]) : "r"(sbase), "r"(r));
    }

    // all CTAs finished init (incl. zeroed h buffers) before any DSMEM store
    asm volatile("barrier.cluster.arrive.aligned;" ::: "memory");
    asm volatile("barrier.cluster.wait.aligned;"   ::: "memory");

    float c[BT] = {0.0f, 0.0f, 0.0f, 0.0f};

    const float bia0 = bias_s[0 * JJ + lane];
    const float bia1 = bias_s[1 * JJ + lane];
    const float bia2 = bias_s[2 * JJ + lane];
    const float bia3 = bias_s[3 * JJ + lane];
    const float wout = Wout_s[lane];

    for (int t = 0; t < TT; ++t) {
        // stage X[:, t, :] (B x P = 1024 floats, 1 float4/thread)
        {
            int b  = tid >> 3;
            int d4 = (tid & 7) << 2;
            float4 v = *reinterpret_cast<const float4*>(&Xg[((size_t)b * TT + t) * PP + d4]);
            *reinterpret_cast<float4*>(&X_s[b * PP + d4]) = v;
        }
        __syncthreads();

        const float* h_cur = smem + ((t & 1) ? OFF_H1 : OFF_H0);
        const uint32_t next_off = (uint32_t)(((t & 1) ? OFF_H0 : OFF_H1) * 4);

        float acc0[BT], acc1[BT], acc2[BT], acc3[BT];
#pragma unroll
        for (int i = 0; i < BT; ++i) { acc0[i] = bia0; acc1[i] = bia1; acc2[i] = bia2; acc3[i] = bia3; }

        // input projection: k over d (32)
#pragma unroll
        for (int dc = 0; dc < PP / 4; ++dc) {
            float4 w0 = *reinterpret_cast<const float4*>(&Wih_s[((0 * 8 + dc) * JJ + lane) * 4]);
            float4 w1 = *reinterpret_cast<const float4*>(&Wih_s[((1 * 8 + dc) * JJ + lane) * 4]);
            float4 w2 = *reinterpret_cast<const float4*>(&Wih_s[((2 * 8 + dc) * JJ + lane) * 4]);
            float4 w3 = *reinterpret_cast<const float4*>(&Wih_s[((3 * 8 + dc) * JJ + lane) * 4]);
#pragma unroll
            for (int i = 0; i < BT; ++i) {
                float4 xv = *reinterpret_cast<const float4*>(&X_s[(b0 + i) * PP + dc * 4]);
                acc0[i] = fmaf(w0.x, xv.x, fmaf(w0.y, xv.y, fmaf(w0.z, xv.z, fmaf(w0.w, xv.w, acc0[i]))));
                acc1[i] = fmaf(w1.x, xv.x, fmaf(w1.y, xv.y, fmaf(w1.z, xv.z, fmaf(w1.w, xv.w, acc1[i]))));
                acc2[i] = fmaf(w2.x, xv.x, fmaf(w2.y, xv.y, fmaf(w2.z, xv.z, fmaf(w2.w, xv.w, acc2[i]))));
                acc3[i] = fmaf(w3.x, xv.x, fmaf(w3.y, xv.y, fmaf(w3.z, xv.z, fmaf(w3.w, xv.w, acc3[i]))));
            }
        }

        // recurrent projection: k over h (128)
#pragma unroll 4
        for (int kc = 0; kc < HH / 4; ++kc) {
            float4 w0 = *reinterpret_cast<const float4*>(&Whh_s[((0 * 32 + kc) * JJ + lane) * 4]);
            float4 w1 = *reinterpret_cast<const float4*>(&Whh_s[((1 * 32 + kc) * JJ + lane) * 4]);
            float4 w2 = *reinterpret_cast<const float4*>(&Whh_s[((2 * 32 + kc) * JJ + lane) * 4]);
            float4 w3 = *reinterpret_cast<const float4*>(&Whh_s[((3 * 32 + kc) * JJ + lane) * 4]);
#pragma unroll
            for (int i = 0; i < BT; ++i) {
                float4 hv = *reinterpret_cast<const float4*>(&h_cur[(b0 + i) * HH + kc * 4]);
                acc0[i] = fmaf(w0.x, hv.x, fmaf(w0.y, hv.y, fmaf(w0.z, hv.z, fmaf(w0.w, hv.w, acc0[i]))));
                acc1[i] = fmaf(w1.x, hv.x, fmaf(w1.y, hv.y, fmaf(w1.z, hv.z, fmaf(w1.w, hv.w, acc1[i]))));
                acc2[i] = fmaf(w2.x, hv.x, fmaf(w2.y, hv.y, fmaf(w2.z, hv.z, fmaf(w2.w, hv.w, acc2[i]))));
                acc3[i] = fmaf(w3.x, hv.x, fmaf(w3.y, hv.y, fmaf(w3.z, hv.z, fmaf(w3.w, hv.w, acc3[i]))));
            }
        }

        // activations, state update, broadcast h to cluster, head partial
        float pout[BT];
#pragma unroll
        for (int i = 0; i < BT; ++i) {
            float ig = sigf(acc0[i]);
            float fg = sigf(acc1[i]);
            float gg = tanhfast(acc2[i]);
            float og = sigf(acc3[i]);
            float cc = fmaf(fg, c[i], ig * gg);
            c[i] = cc;
            float hn = og * tanhfast(cc);
            uint32_t eoff = next_off + ((uint32_t)((b0 + i) * HH + j0 + lane) << 2);
#pragma unroll
            for (int r = 0; r < CHUNK; ++r) {
                asm volatile("st.shared::cluster.f32 [%0], %1;"
                             :: "r"(peer_base[r] + eoff), "f"(hn) : "memory");
            }
            pout[i] = hn * wout;
        }

        // head: reduce over this CTA's 32 j's, accumulate into out
#pragma unroll
        for (int i = 0; i < BT; ++i) {
#pragma unroll
            for (int m = 16; m > 0; m >>= 1)
                pout[i] += __shfl_xor_sync(0xffffffffu, pout[i], m);
        }
        if (lane == 0) {
#pragma unroll
            for (int i = 0; i < BT; ++i)
                atomicAdd(&out[((size_t)(b0 + i) * TT + t) * PP + n], pout[i]);
        }

        // step barrier: publishes DSMEM h stores, also acts as __syncthreads
        asm volatile("barrier.cluster.arrive.aligned;" ::: "memory");
        asm volatile("barrier.cluster.wait.aligned;"   ::: "memory");
    }
}

extern "C" void kernel_launch(void* const* d_in, const int* in_sizes, int n_in,
                              void* d_out, int out_size) {
    const float* X    = (const float*)d_in[0];
    const float* Wih  = (const float*)d_in[1];
    const float* Whh  = (const float*)d_in[2];
    const float* bih  = (const float*)d_in[3];
    const float* bhh  = (const float*)d_in[4];
    const float* Wout = (const float*)d_in[5];
    const float* bout = (const float*)d_in[6];
    float* out = (float*)d_out;

    cudaFuncSetAttribute(clstm_kernel, cudaFuncAttributeMaxDynamicSharedMemorySize, SMEM_BYTES);

    init_out_kernel<<<(BB * TT * PP + 255) / 256, 256>>>(out, bout);
    clstm_kernel<<<PP * CHUNK, NTHREADS, SMEM_BYTES>>>(X, Wih, Whh, bih, bhh, Wout, out);
}

// round 3
// speedup vs baseline: 1.0723x; 1.0723x over previous
#include <cuda_runtime.h>
#include <cstdint>

#define PP 32      // num networks
#define HH 128     // hidden
#define BB 32      // batch
#define TT 256     // seq len
#define CHUNK 4    // CTAs per network (cluster size)
#define JJ 32      // h outputs per CTA
#define NTHREADS 256
#define BT 4       // batches per thread

// ---- shared memory layout (float offsets) ----
#define OFF_WHH   0                       // [4][32 kc][32 j][4 ki]  = 16384
#define SZ_WHH    (4*32*32*4)
#define OFF_WIH   (OFF_WHH + SZ_WHH)      // [4][8 dc][32 j][4 di]   = 4096
#define SZ_WIH    (4*8*32*4)
#define OFF_H0    (OFF_WIH + SZ_WIH)      // [32 b][128 k]           = 4096
#define OFF_H1    (OFF_H0 + BB*HH)        //                         = 4096
#define OFF_X     (OFF_H1 + BB*HH)        // [32 b][32 d]            = 1024
#define OFF_BIAS  (OFF_X + BB*PP)         // [4][32]                 = 128
#define OFF_WOUT  (OFF_BIAS + 4*JJ)       // [32]                    = 32
#define SMEM_FLOATS (OFF_WOUT + JJ)       // 29856 floats
#define SMEM_BYTES (SMEM_FLOATS * 4)      // 119424 bytes

typedef unsigned long long u64;

__device__ __forceinline__ u64 fma2(u64 a, u64 b, u64 c) {
    u64 d;
    asm("fma.rn.f32x2 %0, %1, %2, %3;" : "=l"(d) : "l"(a), "l"(b), "l"(c));
    return d;
}
__device__ __forceinline__ u64 pack2(float lo, float hi) {
    u64 d; asm("mov.b64 %0, {%1, %2};" : "=l"(d) : "f"(lo), "f"(hi)); return d;
}
__device__ __forceinline__ float sum2(u64 a) {
    float lo, hi; asm("mov.b64 {%0, %1}, %2;" : "=f"(lo), "=f"(hi) : "l"(a));
    return lo + hi;
}

__device__ __forceinline__ float sigf(float x) {
    return 1.0f / (1.0f + __expf(-x));
}
__device__ __forceinline__ float tanhfast(float x) {
    return 2.0f / (1.0f + __expf(-2.0f * x)) - 1.0f;
}

__global__ void init_out_kernel(float* __restrict__ out, const float* __restrict__ b_out) {
    int i = blockIdx.x * blockDim.x + threadIdx.x;
    if (i < BB * TT * PP) out[i] = b_out[i & (PP - 1)];
}

extern __shared__ float smem[];

__global__ void __cluster_dims__(CHUNK, 1, 1) __launch_bounds__(NTHREADS, 1)
clstm_kernel(const float* __restrict__ Xg,
             const float* __restrict__ Wih,
             const float* __restrict__ Whh,
             const float* __restrict__ bih,
             const float* __restrict__ bhh,
             const float* __restrict__ Wout,
             float* __restrict__ out)
{
    const int tid  = threadIdx.x;
    const int lane = tid & 31;           // j within this CTA's slice
    const int warp = tid >> 5;           // 8 warps
    const int b0   = warp * BT;          // batches [b0, b0+4)

    uint32_t rank;
    asm("mov.u32 %0, %%cluster_ctarank;" : "=r"(rank));
    const int n  = blockIdx.x >> 2;      // network id
    const int j0 = (int)rank * JJ;       // global j offset of this CTA's slice

    float* Whh_s  = smem + OFF_WHH;
    float* Wih_s  = smem + OFF_WIH;
    float* X_s    = smem + OFF_X;
    float* bias_s = smem + OFF_BIAS;
    float* Wout_s = smem + OFF_WOUT;

    // ---- stage weights (transposed for conflict-free lane loads) ----
    for (int idx = tid; idx < 4 * HH * JJ; idx += NTHREADS) {
        int g   = idx / (HH * JJ);
        int rem = idx - g * (HH * JJ);
        int k   = rem / JJ;
        int j   = rem - k * JJ;
        float v = Whh[((size_t)n * 4 * HH + g * HH + j0 + j) * HH + k];
        Whh_s[((g * 32 + (k >> 2)) * JJ + j) * 4 + (k & 3)] = v;
    }
    for (int idx = tid; idx < 4 * PP * JJ; idx += NTHREADS) {
        int g   = idx / (PP * JJ);
        int rem = idx - g * (PP * JJ);
        int j   = rem / PP;
        int d   = rem - j * PP;
        float v = Wih[((size_t)n * 4 * HH + g * HH + j0 + j) * PP + d];
        Wih_s[((g * 8 + (d >> 2)) * JJ + j) * 4 + (d & 3)] = v;
    }
    for (int idx = tid; idx < 4 * JJ; idx += NTHREADS) {
        int g = idx / JJ, j = idx - g * JJ;
        int row = n * 4 * HH + g * HH + j0 + j;
        bias_s[g * JJ + j] = bih[row] + bhh[row];
    }
    if (tid < JJ) Wout_s[tid] = Wout[n * HH + j0 + tid];
    for (int idx = tid; idx < 2 * BB * HH; idx += NTHREADS) smem[OFF_H0 + idx] = 0.0f;

    uint32_t sbase;
    asm("{ .reg .u64 t0; cvta.to.shared.u64 t0, %1; cvt.u32.u64 %0, t0; }"
        : "=r"(sbase) : "l"(smem));
    uint32_t peer_base[CHUNK];
#pragma unroll
    for (int r = 0; r < CHUNK; ++r) {
        asm("mapa.shared::cluster.u32 %0, %1, %2;" : "=r"(peer_base[r]) : "r"(sbase), "r"(r));
    }

    asm volatile("barrier.cluster.arrive.aligned;" ::: "memory");
    asm volatile("barrier.cluster.wait.aligned;"   ::: "memory");

    float c[BT] = {0.0f, 0.0f, 0.0f, 0.0f};

    const float bia0 = bias_s[0 * JJ + lane];
    const float bia1 = bias_s[1 * JJ + lane];
    const float bia2 = bias_s[2 * JJ + lane];
    const float bia3 = bias_s[3 * JJ + lane];
    const float wout = Wout_s[lane];

    // pointers to this lane's weight columns (16B-aligned)
    const ulonglong2* Wih2 = reinterpret_cast<const ulonglong2*>(Wih_s) + lane;
    const ulonglong2* Whh2 = reinterpret_cast<const ulonglong2*>(Whh_s) + lane;

    // X prefetch register: this thread stages X[b=tid>>3, t, d4=(tid&7)*4]
    const int xb  = tid >> 3;
    const int xd4 = (tid & 7) << 2;
    float4 xreg = *reinterpret_cast<const float4*>(&Xg[((size_t)xb * TT + 0) * PP + xd4]);

    for (int t = 0; t < TT; ++t) {
        // stage prefetched X[:, t, :]
        *reinterpret_cast<float4*>(&X_s[xb * PP + xd4]) = xreg;
        __syncthreads();
        if (t + 1 < TT)
            xreg = *reinterpret_cast<const float4*>(&Xg[((size_t)xb * TT + (t + 1)) * PP + xd4]);

        const float* h_cur = smem + ((t & 1) ? OFF_H1 : OFF_H0);
        const uint32_t next_off = (uint32_t)(((t & 1) ? OFF_H0 : OFF_H1) * 4);

        // f32x2 accumulators: halves hold k-even / k-odd partial sums
        u64 acc0[BT], acc1[BT], acc2[BT], acc3[BT];
#pragma unroll
        for (int i = 0; i < BT; ++i) {
            acc0[i] = pack2(bia0, 0.0f);
            acc1[i] = pack2(bia1, 0.0f);
            acc2[i] = pack2(bia2, 0.0f);
            acc3[i] = pack2(bia3, 0.0f);
        }

        // input projection: k over d (32)
#pragma unroll
        for (int dc = 0; dc < PP / 4; ++dc) {
            ulonglong2 w0 = Wih2[(0 * 8 + dc) * JJ];
            ulonglong2 w1 = Wih2[(1 * 8 + dc) * JJ];
            ulonglong2 w2 = Wih2[(2 * 8 + dc) * JJ];
            ulonglong2 w3 = Wih2[(3 * 8 + dc) * JJ];
#pragma unroll
            for (int i = 0; i < BT; ++i) {
                ulonglong2 xv = *reinterpret_cast<const ulonglong2*>(&X_s[(b0 + i) * PP + dc * 4]);
                acc0[i] = fma2(w0.x, xv.x, acc0[i]); acc0[i] = fma2(w0.y, xv.y, acc0[i]);
                acc1[i] = fma2(w1.x, xv.x, acc1[i]); acc1[i] = fma2(w1.y, xv.y, acc1[i]);
                acc2[i] = fma2(w2.x, xv.x, acc2[i]); acc2[i] = fma2(w2.y, xv.y, acc2[i]);
                acc3[i] = fma2(w3.x, xv.x, acc3[i]); acc3[i] = fma2(w3.y, xv.y, acc3[i]);
            }
        }

        // recurrent projection: k over h (128)
#pragma unroll 8
        for (int kc = 0; kc < HH / 4; ++kc) {
            ulonglong2 w0 = Whh2[(0 * 32 + kc) * JJ];
            ulonglong2 w1 = Whh2[(1 * 32 + kc) * JJ];
            ulonglong2 w2 = Whh2[(2 * 32 + kc) * JJ];
            ulonglong2 w3 = Whh2[(3 * 32 + kc) * JJ];
#pragma unroll
            for (int i = 0; i < BT; ++i) {
                ulonglong2 hv = *reinterpret_cast<const ulonglong2*>(&h_cur[(b0 + i) * HH + kc * 4]);
                acc0[i] = fma2(w0.x, hv.x, acc0[i]); acc0[i] = fma2(w0.y, hv.y, acc0[i]);
                acc1[i] = fma2(w1.x, hv.x, acc1[i]); acc1[i] = fma2(w1.y, hv.y, acc1[i]);
                acc2[i] = fma2(w2.x, hv.x, acc2[i]); acc2[i] = fma2(w2.y, hv.y, acc2[i]);
                acc3[i] = fma2(w3.x, hv.x, acc3[i]); acc3[i] = fma2(w3.y, hv.y, acc3[i]);
            }
        }

        // activations, state update, broadcast h to cluster, head partial
        float pout[BT];
#pragma unroll
        for (int i = 0; i < BT; ++i) {
            float ig = sigf(sum2(acc0[i]));
            float fg = sigf(sum2(acc1[i]));
            float gg = tanhfast(sum2(acc2[i]));
            float og = sigf(sum2(acc3[i]));
            float cc = fmaf(fg, c[i], ig * gg);
            c[i] = cc;
            float hn = og * tanhfast(cc);
            uint32_t eoff = next_off + ((uint32_t)((b0 + i) * HH + j0 + lane) << 2);
#pragma unroll
            for (int r = 0; r < CHUNK; ++r) {
                asm volatile("st.shared::cluster.f32 [%0], %1;"
                             :: "r"(peer_base[r] + eoff), "f"(hn) : "memory");
            }
            pout[i] = hn * wout;
        }

        // head: reduce over this CTA's 32 j's, accumulate into out
#pragma unroll
        for (int i = 0; i < BT; ++i) {
#pragma unroll
            for (int m = 16; m > 0; m >>= 1)
                pout[i] += __shfl_xor_sync(0xffffffffu, pout[i], m);
        }
        if (lane == 0) {
#pragma unroll
            for (int i = 0; i < BT; ++i)
                atomicAdd(&out[((size_t)(b0 + i) * TT + t) * PP + n], pout[i]);
        }

        // step barrier: publishes DSMEM h stores, also acts as __syncthreads
        asm volatile("barrier.cluster.arrive.aligned;" ::: "memory");
        asm volatile("barrier.cluster.wait.aligned;"   ::: "memory");
    }
}

extern "C" void kernel_launch(void* const* d_in, const int* in_sizes, int n_in,
                              void* d_out, int out_size) {
    const float* X    = (const float*)d_in[0];
    const float* Wih  = (const float*)d_in[1];
    const float* Whh  = (const float*)d_in[2];
    const float* bih  = (const float*)d_in[3];
    const float* bhh  = (const float*)d_in[4];
    const float* Wout = (const float*)d_in[5];
    const float* bout = (const float*)d_in[6];
    float* out = (float*)d_out;

    cudaFuncSetAttribute(clstm_kernel, cudaFuncAttributeMaxDynamicSharedMemorySize, SMEM_BYTES);

    init_out_kernel<<<(BB * TT * PP + 255) / 256, 256>>>(out, bout);
    clstm_kernel<<<PP * CHUNK, NTHREADS, SMEM_BYTES>>>(X, Wih, Whh, bih, bhh, Wout, out);
}

// round 7
// speedup vs baseline: 1.6607x; 1.5488x over previous
#include <cuda_runtime.h>
#include <cuda_bf16.h>
#include <cstdint>

#define PP 32      // num networks
#define HH 128     // hidden
#define BB 32      // batch
#define TT 256     // seq len
#define CHUNK 4    // CTAs per network (cluster size)
#define NTHREADS 256
#define KTILES 10  // K = 160 = 10 x 16

// B buffer: per n (batch), PADW words (u32 = packed bf16 k-pair), conflict-free
#define PADW 88
#define BBYTES (32 * PADW * 4)          // 11264 per buffer

// smem byte offsets
#define OFF_BIAS 0                       // 4*32 f32
#define OFF_WOUT 512                     // 32 f32
#define OFF_B0   1024                    // 4 buffers: buf0_hi, buf0_lo, buf1_hi, buf1_lo
#define OFF_S    (1024 + 4 * BBYTES)     // D staging: [4 g][32 jl][34 b] f32
#define S_PAD    34
#define SMEM_BYTES (OFF_S + 4 * 32 * S_PAD * 4)   // 63488

// packed X scratch: [b][t][16 words] for k<32 region, hi and lo
__device__ uint32_t Xp_hi_g[BB * TT * 16];
__device__ uint32_t Xp_lo_g[BB * TT * 16];

__device__ __forceinline__ float sigf(float x) { return 1.0f / (1.0f + __expf(-x)); }
__device__ __forceinline__ float tanhfast(float x) { return 2.0f / (1.0f + __expf(-2.0f * x)) - 1.0f; }

__device__ __forceinline__ uint32_t pack_bf2(float lo_k, float hi_k) {
    unsigned short a = __bfloat16_as_ushort(__float2bfloat16(lo_k));
    unsigned short b = __bfloat16_as_ushort(__float2bfloat16(hi_k));
    return (uint32_t)a | ((uint32_t)b << 16);
}

__device__ __forceinline__ void mma16816(float* d, const uint32_t* a, uint32_t b0, uint32_t b1) {
    asm volatile(
        "mma.sync.aligned.m16n8k16.row.col.f32.bf16.bf16.f32 "
        "{%0,%1,%2,%3}, {%4,%5,%6,%7}, {%8,%9}, {%0,%1,%2,%3};"
        : "+f"(d[0]), "+f"(d[1]), "+f"(d[2]), "+f"(d[3])
        : "r"(a[0]), "r"(a[1]), "r"(a[2]), "r"(a[3]), "r"(b0), "r"(b1));
}

#define CLUSTER_BAR() do { \
    asm volatile("barrier.cluster.arrive.aligned;" ::: "memory"); \
    asm volatile("barrier.cluster.wait.aligned;"   ::: "memory"); } while (0)

__global__ void init_out_kernel(float* __restrict__ out, const float* __restrict__ b_out) {
    int i = blockIdx.x * blockDim.x + threadIdx.x;
    if (i < BB * TT * PP) out[i] = b_out[i & (PP - 1)];
}

// split X into packed hi/lo bf16 word layout: word w of n holds k-pair at
// d0 = (w>>3)*16 + ((w&7)>>1)*2 + (w&1)*8
__global__ void xsplit_kernel(const float* __restrict__ X) {
    int i = blockIdx.x * blockDim.x + threadIdx.x;
    if (i >= BB * TT * 16) return;
    int w = i & 15;
    int bt = i >> 4;              // b*TT + t
    int d0 = ((w >> 3) * 16) + (((w & 7) >> 1) * 2) + ((w & 1) * 8);
    float v0 = X[(size_t)bt * PP + d0];
    float v1 = X[(size_t)bt * PP + d0 + 1];
    __nv_bfloat16 h0 = __float2bfloat16(v0);
    __nv_bfloat16 h1 = __float2bfloat16(v1);
    float l0 = v0 - __bfloat162float(h0);
    float l1 = v1 - __bfloat162float(h1);
    Xp_hi_g[i] = (uint32_t)__bfloat16_as_ushort(h0) | ((uint32_t)__bfloat16_as_ushort(h1) << 16);
    Xp_lo_g[i] = pack_bf2(l0, l1);
}

extern __shared__ char smem_c[];

__global__ void __cluster_dims__(CHUNK, 1, 1) __launch_bounds__(NTHREADS, 1)
clstm_mma_kernel(const float* __restrict__ Wih,
                 const float* __restrict__ Whh,
                 const float* __restrict__ bih,
                 const float* __restrict__ bhh,
                 const float* __restrict__ Wout,
                 float* __restrict__ out)
{
    const int tid  = threadIdx.x;
    const int lane = tid & 31;
    const int wid  = tid >> 5;           // 8 warps
    const int r    = lane >> 2;          // fragment row group
    const int tg   = lane & 3;           // fragment thread-in-group

    uint32_t rank;
    asm("mov.u32 %0, %%cluster_ctarank;" : "=r"(rank));
    const int n  = blockIdx.x >> 2;      // network id
    const int j0 = (int)rank * 32;

    float* S = reinterpret_cast<float*>(smem_c + OFF_S);

    // ---- zero all B buffers (h region must start at 0) ----
    {
        uint4 z = make_uint4(0, 0, 0, 0);
        for (int i = tid; i < 4 * BBYTES / 16; i += NTHREADS)
            reinterpret_cast<uint4*>(smem_c + OFF_B0)[i] = z;
    }

    // ---- bias + wout ----
    for (int idx = tid; idx < 4 * 32; idx += NTHREADS) {
        int g = idx >> 5, jl = idx & 31;
        int row = n * 4 * HH + g * HH + j0 + jl;
        *reinterpret_cast<float*>(smem_c + OFF_BIAS + idx * 4) = bih[row] + bhh[row];
    }
    if (tid < 32) *reinterpret_cast<float*>(smem_c + OFF_WOUT + tid * 4) = Wout[n * HH + j0 + tid];

    // RACE FIX: zero-loop / bias / wout writes must complete before any thread
    // stages X into the zeroed region or reads bias/wout from smem.
    __syncthreads();

    // ---- load A fragments (weights) into registers, hi/lo split ----
    // warp w covers gate-rows m = w*16 + {r, r+8}; gate g = w>>1, jl = m&31
    uint32_t Ahi[KTILES][4], Alo[KTILES][4];
    {
        const int g = wid >> 1;
        const int m0 = wid * 16 + r;
        const int m1 = m0 + 8;
        const int jl0 = m0 & 31, jl1 = m1 & 31;
        const size_t grow0 = (size_t)(n * 4 * HH + g * HH + j0 + jl0);
        const size_t grow1 = (size_t)(n * 4 * HH + g * HH + j0 + jl1);
#pragma unroll
        for (int kt = 0; kt < KTILES; ++kt) {
#pragma unroll
            for (int e = 0; e < 4; ++e) {
                // e: 0 -> (m0, k0), 1 -> (m1, k0), 2 -> (m0, k0+8), 3 -> (m1, k0+8)
                size_t grow = (e & 1) ? grow1 : grow0;
                int k = kt * 16 + tg * 2 + ((e >> 1) * 8);
                float v0, v1;
                if (k < PP) {
                    v0 = Wih[grow * PP + k];
                    v1 = Wih[grow * PP + k + 1];
                } else {
                    v0 = Whh[grow * HH + (k - PP)];
                    v1 = Whh[grow * HH + (k - PP) + 1];
                }
                __nv_bfloat16 h0 = __float2bfloat16(v0);
                __nv_bfloat16 h1 = __float2bfloat16(v1);
                Ahi[kt][e] = (uint32_t)__bfloat16_as_ushort(h0) | ((uint32_t)__bfloat16_as_ushort(h1) << 16);
                Alo[kt][e] = pack_bf2(v0 - __bfloat162float(h0), v1 - __bfloat162float(h1));
            }
        }
    }

    // ---- stage X(t=0) into buffer 0 (after the sync: region is stably zeroed) ----
    {
        int b = tid >> 3, wp = (tid & 7) * 2;
        uint2 vh = *reinterpret_cast<const uint2*>(&Xp_hi_g[((size_t)b * TT + 0) * 16 + wp]);
        uint2 vl = *reinterpret_cast<const uint2*>(&Xp_lo_g[((size_t)b * TT + 0) * 16 + wp]);
        *reinterpret_cast<uint2*>(smem_c + OFF_B0 + (b * PADW + wp) * 4) = vh;
        *reinterpret_cast<uint2*>(smem_c + OFF_B0 + BBYTES + (b * PADW + wp) * 4) = vl;
    }

    // per-thread epilogue constants (post-barrier: values are valid)
    const float biasI = *reinterpret_cast<float*>(smem_c + OFF_BIAS + (0 * 32 + lane) * 4);
    const float biasF = *reinterpret_cast<float*>(smem_c + OFF_BIAS + (1 * 32 + lane) * 4);
    const float biasG = *reinterpret_cast<float*>(smem_c + OFF_BIAS + (2 * 32 + lane) * 4);
    const float biasO = *reinterpret_cast<float*>(smem_c + OFF_BIAS + (3 * 32 + lane) * 4);
    const float wout  = *reinterpret_cast<float*>(smem_c + OFF_WOUT + lane * 4);

    // this lane-pair's h-write WORD offset (even k of the pair): khe = 32 + j0 + (lane & ~1)
    const int khe = PP + j0 + (lane & ~1);
    const uint32_t hwrd4 = (uint32_t)((khe >> 4) * 8 + ((khe >> 1) & 3) * 2 + ((khe >> 3) & 1)) * 4;

    // smem base + peer bases
    uint32_t sbase;
    asm("{ .reg .u64 t0; cvta.to.shared.u64 t0, %1; cvt.u32.u64 %0, t0; }" : "=r"(sbase) : "l"(smem_c));
    uint32_t peer_base[CHUNK];
#pragma unroll
    for (int rr = 0; rr < CHUNK; ++rr)
        asm("mapa.shared::cluster.u32 %0, %1, %2;" : "=r"(peer_base[rr]) : "r"(sbase), "r"(rr));

    float c[4] = {0.0f, 0.0f, 0.0f, 0.0f};
    int buf = 0;

    for (int t = 0; t < TT; ++t) {
        // publish previous-step h stores + X staging across cluster
        CLUSTER_BAR();

        const char* bufhi = smem_c + OFF_B0 + buf * 2 * BBYTES;
        const char* buflo = bufhi + BBYTES;

        // ---- split-GEMM: acc = A_hi*B_hi + A_hi*B_lo + A_lo*B_hi ----
        float acc[4][4];
#pragma unroll
        for (int nt = 0; nt < 4; ++nt)
#pragma unroll
            for (int e = 0; e < 4; ++e) acc[nt][e] = 0.0f;

#pragma unroll
        for (int kt = 0; kt < KTILES; ++kt) {
            uint2 bh[4], bl[4];
#pragma unroll
            for (int nt = 0; nt < 4; ++nt) {
                uint32_t off = ((nt * 8 + r) * PADW + kt * 8 + tg * 2) * 4;
                bh[nt] = *reinterpret_cast<const uint2*>(bufhi + off);
                bl[nt] = *reinterpret_cast<const uint2*>(buflo + off);
            }
#pragma unroll
            for (int nt = 0; nt < 4; ++nt) mma16816(acc[nt], Ahi[kt], bh[nt].x, bh[nt].y);
#pragma unroll
            for (int nt = 0; nt < 4; ++nt) mma16816(acc[nt], Ahi[kt], bl[nt].x, bl[nt].y);
#pragma unroll
            for (int nt = 0; nt < 4; ++nt) mma16816(acc[nt], Alo[kt], bh[nt].x, bh[nt].y);
        }

        // ---- stage D -> S[g][jl][34 b] ----
        {
            const int g = wid >> 1;
            const int jlb = (wid & 1) * 16 + r;
#pragma unroll
            for (int nt = 0; nt < 4; ++nt) {
                int bcol = nt * 8 + tg * 2;
                *reinterpret_cast<float2*>(&S[(g * 32 + jlb) * S_PAD + bcol]) =
                    make_float2(acc[nt][0], acc[nt][1]);
                *reinterpret_cast<float2*>(&S[(g * 32 + jlb + 8) * S_PAD + bcol]) =
                    make_float2(acc[nt][2], acc[nt][3]);
            }
        }
        __syncthreads();

        const uint32_t offB_next = (uint32_t)(OFF_B0 + (buf ^ 1) * 2 * BBYTES);

        // ---- epilogue: activations + state + h broadcast + head ----
        float pout[4];
#pragma unroll
        for (int i = 0; i < 4; ++i) {
            int b = wid * 4 + i;
            float gi = S[(0 * 32 + lane) * S_PAD + b] + biasI;
            float gf = S[(1 * 32 + lane) * S_PAD + b] + biasF;
            float gg = S[(2 * 32 + lane) * S_PAD + b] + biasG;
            float go = S[(3 * 32 + lane) * S_PAD + b] + biasO;
            float ii = sigf(gi);
            float ff = sigf(gf);
            float g2 = tanhfast(gg);
            float oo = sigf(go);
            float cc = fmaf(ff, c[i], ii * g2);
            c[i] = cc;
            float h = oo * tanhfast(cc);

            __nv_bfloat16 hhb = __float2bfloat16(h);
            float rem = h - __bfloat162float(hhb);
            uint32_t vh = (uint32_t)__bfloat16_as_ushort(hhb);
            uint32_t vl = (uint32_t)__bfloat16_as_ushort(__float2bfloat16(rem));

            // pair up the two bf16 halves of each 32-bit B-word inside the warp
            uint32_t vhp = __shfl_down_sync(0xffffffffu, vh, 1);
            uint32_t vlp = __shfl_down_sync(0xffffffffu, vl, 1);
            if (!(lane & 1)) {
                uint32_t wordh = vh | (vhp << 16);
                uint32_t wordl = vl | (vlp << 16);
                uint32_t oh = offB_next + (uint32_t)b * (PADW * 4) + hwrd4;
                uint32_t ol = oh + BBYTES;
                // own CTA via plain shared store
                *reinterpret_cast<uint32_t*>(smem_c + oh) = wordh;
                *reinterpret_cast<uint32_t*>(smem_c + ol) = wordl;
                // peers via full-word cluster stores
#pragma unroll
                for (int rr = 0; rr < CHUNK; ++rr) {
                    if (rr != (int)rank) {
                        asm volatile("st.shared::cluster.u32 [%0], %1;" :: "r"(peer_base[rr] + oh), "r"(wordh) : "memory");
                        asm volatile("st.shared::cluster.u32 [%0], %1;" :: "r"(peer_base[rr] + ol), "r"(wordl) : "memory");
                    }
                }
            }
            pout[i] = h * wout;
        }

        // head: reduce this CTA's 32 j's, accumulate to out
#pragma unroll
        for (int i = 0; i < 4; ++i) {
#pragma unroll
            for (int m = 16; m > 0; m >>= 1)
                pout[i] += __shfl_xor_sync(0xffffffffu, pout[i], m);
        }
        if (lane == 0) {
#pragma unroll
            for (int i = 0; i < 4; ++i)
                atomicAdd(&out[((size_t)(wid * 4 + i) * TT + t) * PP + n], pout[i]);
        }

        // ---- stage X(t+1) into next buffer (local, disjoint from h region) ----
        {
            int tn = (t + 1 < TT) ? (t + 1) : t;
            int b = tid >> 3, wp = (tid & 7) * 2;
            uint2 vh = *reinterpret_cast<const uint2*>(&Xp_hi_g[((size_t)b * TT + tn) * 16 + wp]);
            uint2 vl = *reinterpret_cast<const uint2*>(&Xp_lo_g[((size_t)b * TT + tn) * 16 + wp]);
            *reinterpret_cast<uint2*>(smem_c + offB_next + (b * PADW + wp) * 4) = vh;
            *reinterpret_cast<uint2*>(smem_c + offB_next + BBYTES + (b * PADW + wp) * 4) = vl;
        }

        buf ^= 1;
    }
}

extern "C" void kernel_launch(void* const* d_in, const int* in_sizes, int n_in,
                              void* d_out, int out_size) {
    const float* X    = (const float*)d_in[0];
    const float* Wih  = (const float*)d_in[1];
    const float* Whh  = (const float*)d_in[2];
    const float* bih  = (const float*)d_in[3];
    const float* bhh  = (const float*)d_in[4];
    const float* Wout = (const float*)d_in[5];
    const float* bout = (const float*)d_in[6];
    float* out = (float*)d_out;

    cudaFuncSetAttribute(clstm_mma_kernel, cudaFuncAttributeMaxDynamicSharedMemorySize, SMEM_BYTES);

    init_out_kernel<<<(BB * TT * PP + 255) / 256, 256>>>(out, bout);
    xsplit_kernel<<<(BB * TT * 16 + 255) / 256, 256>>>(X);
    clstm_mma_kernel<<<PP * CHUNK, NTHREADS, SMEM_BYTES>>>(Wih, Whh, bih, bhh, Wout, out);
}

// round 8
// speedup vs baseline: 2.4494x; 1.4749x over previous
#include <cuda_runtime.h>
#include <cuda_bf16.h>
#include <cstdint>

#define PP 32      // num networks
#define HH 128     // hidden
#define BB 32      // batch
#define TT 256     // seq len
#define CHUNK 4    // CTAs per network (cluster size)
#define NTHREADS 256
#define KTILES 10  // K = 160 = 10 x 16

// B buffer: per n (batch), PADW words (u32 = packed bf16 k-pair), conflict-free
#define PADW 88
#define BBYTES (32 * PADW * 4)          // 11264 per buffer

// smem byte offsets
#define OFF_BIAS 0                       // 4*32 f32
#define OFF_WOUT 512                     // 32 f32
#define OFF_B0   1024                    // 4 buffers: buf0_hi, buf0_lo, buf1_hi, buf1_lo
#define OFF_S    (1024 + 4 * BBYTES)     // D staging: [4 g][32 jl][34 b] f32
#define S_PAD    34
#define SMEM_BYTES (OFF_S + 4 * 32 * S_PAD * 4)   // 63488

// packed X scratch: [b][t][16 words] for k<32 region, hi and lo
__device__ uint32_t Xp_hi_g[BB * TT * 16];
__device__ uint32_t Xp_lo_g[BB * TT * 16];

__device__ __forceinline__ float tanha(float x) {
    float y; asm("tanh.approx.f32 %0, %1;" : "=f"(y) : "f"(x)); return y;
}
__device__ __forceinline__ float sigf(float x) {
    return fmaf(0.5f, tanha(0.5f * x), 0.5f);
}

__device__ __forceinline__ uint32_t pack_bf2(float lo_k, float hi_k) {
    unsigned short a = __bfloat16_as_ushort(__float2bfloat16(lo_k));
    unsigned short b = __bfloat16_as_ushort(__float2bfloat16(hi_k));
    return (uint32_t)a | ((uint32_t)b << 16);
}

__device__ __forceinline__ void mma16816(float* d, const uint32_t* a, uint32_t b0, uint32_t b1) {
    asm volatile(
        "mma.sync.aligned.m16n8k16.row.col.f32.bf16.bf16.f32 "
        "{%0,%1,%2,%3}, {%4,%5,%6,%7}, {%8,%9}, {%0,%1,%2,%3};"
        : "+f"(d[0]), "+f"(d[1]), "+f"(d[2]), "+f"(d[3])
        : "r"(a[0]), "r"(a[1]), "r"(a[2]), "r"(a[3]), "r"(b0), "r"(b1));
}

#define CLUSTER_ARRIVE() asm volatile("barrier.cluster.arrive.aligned;" ::: "memory")
#define CLUSTER_WAIT()   asm volatile("barrier.cluster.wait.aligned;"   ::: "memory")

__global__ void init_out_kernel(float* __restrict__ out, const float* __restrict__ b_out) {
    int i = blockIdx.x * blockDim.x + threadIdx.x;
    if (i < BB * TT * PP) out[i] = b_out[i & (PP - 1)];
}

// split X into packed hi/lo bf16 word layout: word w of n holds k-pair at
// d0 = (w>>3)*16 + ((w&7)>>1)*2 + (w&1)*8
__global__ void xsplit_kernel(const float* __restrict__ X) {
    int i = blockIdx.x * blockDim.x + threadIdx.x;
    if (i >= BB * TT * 16) return;
    int w = i & 15;
    int bt = i >> 4;              // b*TT + t
    int d0 = ((w >> 3) * 16) + (((w & 7) >> 1) * 2) + ((w & 1) * 8);
    float v0 = X[(size_t)bt * PP + d0];
    float v1 = X[(size_t)bt * PP + d0 + 1];
    __nv_bfloat16 h0 = __float2bfloat16(v0);
    __nv_bfloat16 h1 = __float2bfloat16(v1);
    float l0 = v0 - __bfloat162float(h0);
    float l1 = v1 - __bfloat162float(h1);
    Xp_hi_g[i] = (uint32_t)__bfloat16_as_ushort(h0) | ((uint32_t)__bfloat16_as_ushort(h1) << 16);
    Xp_lo_g[i] = pack_bf2(l0, l1);
}

extern __shared__ char smem_c[];

__global__ void __cluster_dims__(CHUNK, 1, 1) __launch_bounds__(NTHREADS, 1)
clstm_mma_kernel(const float* __restrict__ Wih,
                 const float* __restrict__ Whh,
                 const float* __restrict__ bih,
                 const float* __restrict__ bhh,
                 const float* __restrict__ Wout,
                 float* __restrict__ out)
{
    const int tid  = threadIdx.x;
    const int lane = tid & 31;
    const int wid  = tid >> 5;           // 8 warps
    const int r    = lane >> 2;          // fragment row group
    const int tg   = lane & 3;           // fragment thread-in-group

    uint32_t rank;
    asm("mov.u32 %0, %%cluster_ctarank;" : "=r"(rank));
    const int n  = blockIdx.x >> 2;      // network id
    const int j0 = (int)rank * 32;

    float* S = reinterpret_cast<float*>(smem_c + OFF_S);

    // ---- zero all B buffers (h region must start at 0) ----
    {
        uint4 z = make_uint4(0, 0, 0, 0);
        for (int i = tid; i < 4 * BBYTES / 16; i += NTHREADS)
            reinterpret_cast<uint4*>(smem_c + OFF_B0)[i] = z;
    }

    // ---- bias + wout ----
    for (int idx = tid; idx < 4 * 32; idx += NTHREADS) {
        int g = idx >> 5, jl = idx & 31;
        int row = n * 4 * HH + g * HH + j0 + jl;
        *reinterpret_cast<float*>(smem_c + OFF_BIAS + idx * 4) = bih[row] + bhh[row];
    }
    if (tid < 32) *reinterpret_cast<float*>(smem_c + OFF_WOUT + tid * 4) = Wout[n * HH + j0 + tid];

    // zero-loop / bias / wout writes must complete before X staging or bias reads
    __syncthreads();

    // ---- load A fragments (weights) into registers, hi/lo split ----
    // warp w covers gate-rows m = w*16 + {r, r+8}; gate g = w>>1, jl = m&31
    uint32_t Ahi[KTILES][4], Alo[KTILES][4];
    {
        const int g = wid >> 1;
        const int m0 = wid * 16 + r;
        const int m1 = m0 + 8;
        const int jl0 = m0 & 31, jl1 = m1 & 31;
        const size_t grow0 = (size_t)(n * 4 * HH + g * HH + j0 + jl0);
        const size_t grow1 = (size_t)(n * 4 * HH + g * HH + j0 + jl1);
#pragma unroll
        for (int kt = 0; kt < KTILES; ++kt) {
#pragma unroll
            for (int e = 0; e < 4; ++e) {
                // e: 0 -> (m0, k0), 1 -> (m1, k0), 2 -> (m0, k0+8), 3 -> (m1, k0+8)
                size_t grow = (e & 1) ? grow1 : grow0;
                int k = kt * 16 + tg * 2 + ((e >> 1) * 8);
                float v0, v1;
                if (k < PP) {
                    v0 = Wih[grow * PP + k];
                    v1 = Wih[grow * PP + k + 1];
                } else {
                    v0 = Whh[grow * HH + (k - PP)];
                    v1 = Whh[grow * HH + (k - PP) + 1];
                }
                __nv_bfloat16 h0 = __float2bfloat16(v0);
                __nv_bfloat16 h1 = __float2bfloat16(v1);
                Ahi[kt][e] = (uint32_t)__bfloat16_as_ushort(h0) | ((uint32_t)__bfloat16_as_ushort(h1) << 16);
                Alo[kt][e] = pack_bf2(v0 - __bfloat162float(h0), v1 - __bfloat162float(h1));
            }
        }
    }

    // ---- stage X(t=0) into buffer 0 (after the sync: region is stably zeroed) ----
    const int xb  = tid >> 3;
    const int xwp = (tid & 7) * 2;
    {
        uint2 vh = *reinterpret_cast<const uint2*>(&Xp_hi_g[((size_t)xb * TT + 0) * 16 + xwp]);
        uint2 vl = *reinterpret_cast<const uint2*>(&Xp_lo_g[((size_t)xb * TT + 0) * 16 + xwp]);
        *reinterpret_cast<uint2*>(smem_c + OFF_B0 + (xb * PADW + xwp) * 4) = vh;
        *reinterpret_cast<uint2*>(smem_c + OFF_B0 + BBYTES + (xb * PADW + xwp) * 4) = vl;
    }

    // per-thread epilogue constants (post-barrier: values are valid)
    const float biasI = *reinterpret_cast<float*>(smem_c + OFF_BIAS + (0 * 32 + lane) * 4);
    const float biasF = *reinterpret_cast<float*>(smem_c + OFF_BIAS + (1 * 32 + lane) * 4);
    const float biasG = *reinterpret_cast<float*>(smem_c + OFF_BIAS + (2 * 32 + lane) * 4);
    const float biasO = *reinterpret_cast<float*>(smem_c + OFF_BIAS + (3 * 32 + lane) * 4);
    const float wout  = *reinterpret_cast<float*>(smem_c + OFF_WOUT + lane * 4);

    // this lane-pair's h-write WORD offset (even k of the pair): khe = 32 + j0 + (lane & ~1)
    const int khe = PP + j0 + (lane & ~1);
    const uint32_t hwrd4 = (uint32_t)((khe >> 4) * 8 + ((khe >> 1) & 3) * 2 + ((khe >> 3) & 1)) * 4;

    // smem base + peer bases
    uint32_t sbase;
    asm("{ .reg .u64 t0; cvta.to.shared.u64 t0, %1; cvt.u32.u64 %0, t0; }" : "=r"(sbase) : "l"(smem_c));
    uint32_t peer_base[CHUNK];
#pragma unroll
    for (int rr = 0; rr < CHUNK; ++rr)
        asm("mapa.shared::cluster.u32 %0, %1, %2;" : "=r"(peer_base[rr]) : "r"(sbase), "r"(rr));

    float c[4] = {0.0f, 0.0f, 0.0f, 0.0f};
    int buf = 0;

    // init done: release local init stores to the cluster (arrive #1)
    CLUSTER_ARRIVE();

    for (int t = 0; t < TT; ++t) {
        // prefetch X(t+1) from global BEFORE the wait — latency hidden by barrier+MMA
        int tn = (t + 1 < TT) ? (t + 1) : t;
        uint2 pvh = *reinterpret_cast<const uint2*>(&Xp_hi_g[((size_t)xb * TT + tn) * 16 + xwp]);
        uint2 pvl = *reinterpret_cast<const uint2*>(&Xp_lo_g[((size_t)xb * TT + tn) * 16 + xwp]);

        // wait: all CTAs published h(t) + X(t) stores (arrive #(t+1))
        CLUSTER_WAIT();

        const char* bufhi = smem_c + OFF_B0 + buf * 2 * BBYTES;
        const char* buflo = bufhi + BBYTES;

        // ---- split-GEMM: acc = A_hi*B_hi + A_hi*B_lo + A_lo*B_hi ----
        float acc[4][4];
#pragma unroll
        for (int nt = 0; nt < 4; ++nt)
#pragma unroll
            for (int e = 0; e < 4; ++e) acc[nt][e] = 0.0f;

#pragma unroll
        for (int kt = 0; kt < KTILES; ++kt) {
            uint2 bh[4], bl[4];
#pragma unroll
            for (int nt = 0; nt < 4; ++nt) {
                uint32_t off = ((nt * 8 + r) * PADW + kt * 8 + tg * 2) * 4;
                bh[nt] = *reinterpret_cast<const uint2*>(bufhi + off);
                bl[nt] = *reinterpret_cast<const uint2*>(buflo + off);
            }
#pragma unroll
            for (int nt = 0; nt < 4; ++nt) mma16816(acc[nt], Ahi[kt], bh[nt].x, bh[nt].y);
#pragma unroll
            for (int nt = 0; nt < 4; ++nt) mma16816(acc[nt], Ahi[kt], bl[nt].x, bl[nt].y);
#pragma unroll
            for (int nt = 0; nt < 4; ++nt) mma16816(acc[nt], Alo[kt], bh[nt].x, bh[nt].y);
        }

        // ---- stage D -> S[g][jl][34 b] ----
        {
            const int g = wid >> 1;
            const int jlb = (wid & 1) * 16 + r;
#pragma unroll
            for (int nt = 0; nt < 4; ++nt) {
                int bcol = nt * 8 + tg * 2;
                *reinterpret_cast<float2*>(&S[(g * 32 + jlb) * S_PAD + bcol]) =
                    make_float2(acc[nt][0], acc[nt][1]);
                *reinterpret_cast<float2*>(&S[(g * 32 + jlb + 8) * S_PAD + bcol]) =
                    make_float2(acc[nt][2], acc[nt][3]);
            }
        }
        __syncthreads();

        const uint32_t offB_next = (uint32_t)(OFF_B0 + (buf ^ 1) * 2 * BBYTES);

        // ---- epilogue: activations + state + h broadcast ----
        float pout[4];
#pragma unroll
        for (int i = 0; i < 4; ++i) {
            int b = wid * 4 + i;
            float gi = S[(0 * 32 + lane) * S_PAD + b] + biasI;
            float gf = S[(1 * 32 + lane) * S_PAD + b] + biasF;
            float gg = S[(2 * 32 + lane) * S_PAD + b] + biasG;
            float go = S[(3 * 32 + lane) * S_PAD + b] + biasO;
            float ii = sigf(gi);
            float ff = sigf(gf);
            float g2 = tanha(gg);
            float oo = sigf(go);
            float cc = fmaf(ff, c[i], ii * g2);
            c[i] = cc;
            float h = oo * tanha(cc);

            __nv_bfloat16 hhb = __float2bfloat16(h);
            float rem = h - __bfloat162float(hhb);
            uint32_t vh = (uint32_t)__bfloat16_as_ushort(hhb);
            uint32_t vl = (uint32_t)__bfloat16_as_ushort(__float2bfloat16(rem));

            // pair up the two bf16 halves of each 32-bit B-word inside the warp
            uint32_t vhp = __shfl_down_sync(0xffffffffu, vh, 1);
            uint32_t vlp = __shfl_down_sync(0xffffffffu, vl, 1);
            if (!(lane & 1)) {
                uint32_t wordh = vh | (vhp << 16);
                uint32_t wordl = vl | (vlp << 16);
                uint32_t oh = offB_next + (uint32_t)b * (PADW * 4) + hwrd4;
                uint32_t ol = oh + BBYTES;
                // own CTA via plain shared store
                *reinterpret_cast<uint32_t*>(smem_c + oh) = wordh;
                *reinterpret_cast<uint32_t*>(smem_c + ol) = wordl;
                // peers via full-word cluster stores
#pragma unroll
                for (int rr = 0; rr < CHUNK; ++rr) {
                    if (rr != (int)rank) {
                        asm volatile("st.shared::cluster.u32 [%0], %1;" :: "r"(peer_base[rr] + oh), "r"(wordh) : "memory");
                        asm volatile("st.shared::cluster.u32 [%0], %1;" :: "r"(peer_base[rr] + ol), "r"(wordl) : "memory");
                    }
                }
            }
            pout[i] = h * wout;
        }

        // ---- stage X(t+1) from prefetch regs into next buffer ----
        *reinterpret_cast<uint2*>(smem_c + offB_next + (xb * PADW + xwp) * 4) = pvh;
        *reinterpret_cast<uint2*>(smem_c + offB_next + BBYTES + (xb * PADW + xwp) * 4) = pvl;

        // release this step's stores to the cluster; head work hides under peer skew
        CLUSTER_ARRIVE();

        // head: reduce this CTA's 32 j's, accumulate to out (off critical path)
#pragma unroll
        for (int i = 0; i < 4; ++i) {
#pragma unroll
            for (int m = 16; m > 0; m >>= 1)
                pout[i] += __shfl_xor_sync(0xffffffffu, pout[i], m);
        }
        if (lane == 0) {
#pragma unroll
            for (int i = 0; i < 4; ++i)
                atomicAdd(&out[((size_t)(wid * 4 + i) * TT + t) * PP + n], pout[i]);
        }

        buf ^= 1;
    }

    // consume the final arrive; no CTA exits while peer stores may be in flight
    CLUSTER_WAIT();
}

extern "C" void kernel_launch(void* const* d_in, const int* in_sizes, int n_in,
                              void* d_out, int out_size) {
    const float* X    = (const float*)d_in[0];
    const float* Wih  = (const float*)d_in[1];
    const float* Whh  = (const float*)d_in[2];
    const float* bih  = (const float*)d_in[3];
    const float* bhh  = (const float*)d_in[4];
    const float* Wout = (const float*)d_in[5];
    const float* bout = (const float*)d_in[6];
    float* out = (float*)d_out;

    cudaFuncSetAttribute(clstm_mma_kernel, cudaFuncAttributeMaxDynamicSharedMemorySize, SMEM_BYTES);

    init_out_kernel<<<(BB * TT * PP + 255) / 256, 256>>>(out, bout);
    xsplit_kernel<<<(BB * TT * 16 + 255) / 256, 256>>>(X);
    clstm_mma_kernel<<<PP * CHUNK, NTHREADS, SMEM_BYTES>>>(Wih, Whh, bih, bhh, Wout, out);
}